// round 7
// baseline (speedup 1.0000x reference)
#include <cuda_runtime.h>
#include <cstdint>

// Problem constants
#define BB 4
#define CC 128
#define HH 64
#define WW 128
#define DD 9                  // 9 row-offsets x 9 col-offsets
#define CH 4                  // channels per smem chunk
#define CHALF 64              // channels per half-warp-pair
#define NCHUNK (CHALF / CH)   // 16 chunks per warp
#define TROW 136              // 8 zero-pad floats + 128 data floats
#define CHBUF (CH * TROW)     // 544 floats
#define WARPBUF (2 * CHBUF)   // 1088 floats, double-buffered, per warp
#define NW 18                 // 9 oy x 2 channel-halves
#define NTHREADS (NW * 32)    // 576
#define SMEM_FLOATS (NW * WARPBUF)          // 19584 floats
#define SMEM_BYTES (SMEM_FLOATS * 4)        // 78336 B
#define REDSTRIDE 37          // conflict-free lane stride for reduction staging

__device__ __forceinline__ void cp_async16(float* smem_dst, const float* gmem_src) {
    unsigned sm = (unsigned)__cvta_generic_to_shared(smem_dst);
    asm volatile("cp.async.cg.shared.global [%0], [%1], 16;\n" :: "r"(sm), "l"(gmem_src));
}
__device__ __forceinline__ void cp_commit() {
    asm volatile("cp.async.commit_group;\n" ::: "memory");
}
__device__ __forceinline__ void cp_wait1() {
    asm volatile("cp.async.wait_group 1;\n" ::: "memory");
}
__device__ __forceinline__ void cp_wait0() {
    asm volatile("cp.async.wait_group 0;\n" ::: "memory");
}

__device__ __forceinline__ void stage(const float* __restrict__ trowp, float* wbase,
                                      int k, int buf, int lane) {
    const float* g = trowp + (size_t)k * CH * HH * WW;
    float* s = wbase + buf * CHBUF + 8 + lane * 4;
    #pragma unroll
    for (int u = 0; u < CH; u++)
        cp_async16(s + u * TROW, g + (size_t)u * HH * WW);
    cp_commit();
}

__global__ __launch_bounds__(NTHREADS, 1)
void cost_volume_kernel(const float* __restrict__ src,
                        const float* __restrict__ tgt,
                        float* __restrict__ out) {
    extern __shared__ float smem[];
    const int bh   = blockIdx.x;
    const int b    = bh >> 6;        // / HH
    const int h    = bh & 63;
    const int tid  = threadIdx.x;
    const int warp = tid >> 5;       // 0..17
    const int oy   = warp >> 1;      // 0..8
    const int half = warp & 1;       // channel half
    const int lane = tid & 31;       // owns w = 4*lane .. 4*lane+3

    const int trow = h + oy - 8;
    float* op = out + ((size_t)(b * 81 + oy * DD) * HH + h) * WW + lane * 4;

    if (trow < 0) {
        if (half == 0) {
            float4 z = make_float4(0.f, 0.f, 0.f, 0.f);
            #pragma unroll
            for (int d = 0; d < DD; d++)
                *(float4*)(op + (size_t)d * HH * WW) = z;
        }
        return;   // exited threads are excluded from later __syncthreads (sm_70+)
    }

    float* wbase = smem + warp * WARPBUF;

    // Zero the 8-float left pads of all 2*CH rows of this warp (once).
    if (lane < 16) {
        int r = lane >> 1;
        int f = lane & 1;
        int buf = r >> 2, c = r & 3;
        *((float4*)(wbase + buf * CHBUF + c * TROW) + f) = make_float4(0.f, 0.f, 0.f, 0.f);
    }
    __syncwarp();

    // Per-warp global bases (channel offset by half*CHALF)
    const float* trowp = tgt + (((size_t)(b * CC + half * CHALF)) * HH + trow) * WW + lane * 4;
    const float* srow  = src + (((size_t)(b * CC + half * CHALF)) * HH + h) * WW + lane * 4;

    float acc[4][DD];
    #pragma unroll
    for (int wi = 0; wi < 4; wi++)
        #pragma unroll
        for (int d = 0; d < DD; d++) acc[wi][d] = 0.f;

    stage(trowp, wbase, 0, 0, lane);

    #pragma unroll 2
    for (int k = 0; k < NCHUNK; k++) {
        const int buf = k & 1;
        if (k + 1 < NCHUNK) {
            stage(trowp, wbase, k + 1, buf ^ 1, lane);
            cp_wait1();
        } else {
            cp_wait0();
        }
        __syncwarp();

        const float* Tb = wbase + buf * CHBUF + lane * 4;
        const float* Sp = srow + (size_t)k * CH * HH * WW;
        #pragma unroll
        for (int c = 0; c < CH; c++) {
            float4 s4 = *(const float4*)(Sp + (size_t)c * HH * WW);   // LDG.128
            float4 t0 = *(const float4*)(Tb + c * TROW);
            float4 t1 = *(const float4*)(Tb + c * TROW + 4);
            float4 t2 = *(const float4*)(Tb + c * TROW + 8);
            float s[4]  = {s4.x, s4.y, s4.z, s4.w};
            float t[12] = {t0.x, t0.y, t0.z, t0.w,
                           t1.x, t1.y, t1.z, t1.w,
                           t2.x, t2.y, t2.z, t2.w};
            #pragma unroll
            for (int wi = 0; wi < 4; wi++)
                #pragma unroll
                for (int d = 0; d < DD; d++)
                    acc[wi][d] = fmaf(s[wi], t[wi + d], acc[wi][d]);
        }
        __syncwarp();
    }

    // ---- Pairwise reduction across the two channel-halves of each oy ----
    // All surviving warps have finished compute; smem buffers are dead.
    __syncthreads();
    // Staging area (reuses smem from offset 0): slot per (oy, lane), stride 37.
    float* red = smem + ((size_t)oy * 32 + lane) * REDSTRIDE;
    if (half == 1) {
        #pragma unroll
        for (int wi = 0; wi < 4; wi++)
            #pragma unroll
            for (int d = 0; d < DD; d++)
                red[wi * DD + d] = acc[wi][d];
    }
    __syncthreads();
    if (half == 0) {
        #pragma unroll
        for (int d = 0; d < DD; d++) {
            float4 v = make_float4(acc[0][d] + red[0 * DD + d],
                                   acc[1][d] + red[1 * DD + d],
                                   acc[2][d] + red[2 * DD + d],
                                   acc[3][d] + red[3 * DD + d]);
            *(float4*)(op + (size_t)d * HH * WW) = v;
        }
    }
}

extern "C" void kernel_launch(void* const* d_in, const int* in_sizes, int n_in,
                              void* d_out, int out_size) {
    const float* src = (const float*)d_in[0];
    const float* tgt = (const float*)d_in[1];
    float* out = (float*)d_out;

    cudaFuncSetAttribute(cost_volume_kernel,
                         cudaFuncAttributeMaxDynamicSharedMemorySize, SMEM_BYTES);
    cost_volume_kernel<<<BB * HH, NTHREADS, SMEM_BYTES>>>(src, tgt, out);
}